// round 6
// baseline (speedup 1.0000x reference)
#include <cuda_runtime.h>
#include <math_constants.h>

#define BB 8
#define NN 50000
#define LL 512
#define RR 5
#define GPB 256                 // blocks per batch in the fused kernel
#define WPB 8                   // warps per block
#define WARPS_PER_BATCH (GPB * WPB)   // 2048

#define H1 200
#define H2 100
#define CC 2

// partial top/bot candidates: one sorted 5+5 set per block per batch
__device__ float g_part_top[BB * GPB * RR];   // sorted descending per 5-group
__device__ float g_part_bot[BB * GPB * RR];   // sorted ascending per 5-group

// collapsed affine MLP: out = cat @ W_eff + b_eff
__device__ float g_Weff[2 * RR * CC];         // [10][2]
__device__ float g_beff[CC];

// ---------------------------------------------------------------------------
// sorted-insertion helpers
// ---------------------------------------------------------------------------
__device__ __forceinline__ void insert_max(float* arr, float v) {
    if (v > arr[RR - 1]) {
        arr[RR - 1] = v;
#pragma unroll
        for (int j = RR - 1; j > 0; j--) {
            if (arr[j] > arr[j - 1]) {
                float t = arr[j]; arr[j] = arr[j - 1]; arr[j - 1] = t;
            }
        }
    }
}
__device__ __forceinline__ void insert_min(float* arr, float v) {
    if (v < arr[RR - 1]) {
        arr[RR - 1] = v;
#pragma unroll
        for (int j = RR - 1; j > 0; j--) {
            if (arr[j] < arr[j - 1]) {
                float t = arr[j]; arr[j] = arr[j - 1]; arr[j - 1] = t;
            }
        }
    }
}

// merge two sorted-descending 5-lists -> top 5
__device__ __forceinline__ void merge_desc5(const float* a, const float* b, float* o) {
    int i = 0, j = 0;
#pragma unroll
    for (int k = 0; k < RR; k++) {
        float av = a[i], bv = b[j];
        bool ta = (av >= bv);
        o[k] = ta ? av : bv;
        i += ta; j += !ta;
    }
}
// merge two sorted-ascending 5-lists -> bottom 5
__device__ __forceinline__ void merge_asc5(const float* a, const float* b, float* o) {
    int i = 0, j = 0;
#pragma unroll
    for (int k = 0; k < RR; k++) {
        float av = a[i], bv = b[j];
        bool ta = (av <= bv);
        o[k] = ta ? av : bv;
        i += ta; j += !ta;
    }
}

// ---------------------------------------------------------------------------
// Fused kernel: scores + running top-5/bot-5 + (one extra block) MLP collapse.
// grid = (GPB, BB+1), 256 threads. Block row y==BB, x==0 computes W_eff/b_eff
// overlapped under the DRAM-bound score streaming.
// ---------------------------------------------------------------------------
__global__ __launch_bounds__(256) void chowder_scores_topk_kernel(
    const float* __restrict__ x,
    const float* __restrict__ conv_w,
    const float* __restrict__ conv_b,
    const float* __restrict__ w1, const float* __restrict__ b1,
    const float* __restrict__ w2, const float* __restrict__ b2,
    const float* __restrict__ w3, const float* __restrict__ b3)
{
    __shared__ float4 ws[LL / 4];
    __shared__ float stop[WPB * RR];
    __shared__ float sbot[WPB * RR];
    // precompute-block scratch (only written by the y==BB block)
    __shared__ float sW12[2 * RR * H2];   // [10][100] = W1@W2
    __shared__ float sb12[H2];            // b1@W2 + b2

    const int tid  = threadIdx.x;
    const int warp = tid >> 5;
    const int lane = tid & 31;
    const int b    = blockIdx.y;

    if (b == BB) {
        // ---------------- MLP collapse block ----------------
        if (blockIdx.x != 0) return;

        // Stage A: threads 0..99, o = tid: stream w2 column o once,
        // accumulate 10 W12 rows + b12 (w1/b1 loads are lane-uniform -> L1 broadcast)
        if (tid < H2) {
            float acc[2 * RR];
            float accb = 0.0f;
#pragma unroll
            for (int i = 0; i < 2 * RR; i++) acc[i] = 0.0f;
            for (int k = 0; k < H1; k++) {
                float wv = w2[k * H2 + tid];
#pragma unroll
                for (int i = 0; i < 2 * RR; i++)
                    acc[i] = fmaf(w1[i * H1 + k], wv, acc[i]);
                accb = fmaf(b1[k], wv, accb);
            }
#pragma unroll
            for (int i = 0; i < 2 * RR; i++) sW12[i * H2 + tid] = acc[i];
            sb12[tid] = accb + b2[tid];
        }
        __syncthreads();

        // Stage B: W_eff[i][c], b_eff[c]
        if (tid < 2 * RR * CC) {
            const int i = tid / CC, c = tid % CC;
            float a = 0.0f;
            for (int o = 0; o < H2; o++)
                a = fmaf(sW12[i * H2 + o], w3[o * CC + c], a);
            g_Weff[i * CC + c] = a;
        }
        if (tid >= 32 && tid < 32 + CC) {
            const int c = tid - 32;
            float a = b3[c];
            for (int o = 0; o < H2; o++)
                a = fmaf(sb12[o], w3[o * CC + c], a);
            g_beff[c] = a;
        }
        return;
    }

    // ---------------- score streaming + top/bot-5 (at HBM roofline) ----------------
    for (int i = tid; i < LL / 4; i += blockDim.x)
        ws[i] = reinterpret_cast<const float4*>(conv_w)[i];
    __syncthreads();

    float4 w0  = ws[0 * 32 + lane];
    float4 w1r = ws[1 * 32 + lane];
    float4 w2r = ws[2 * 32 + lane];
    float4 w3r = ws[3 * 32 + lane];

    const int gw = blockIdx.x * WPB + warp;
    const float cb = conv_b[0];
    const float* __restrict__ xb = x + (long long)b * NN * LL;

    float top[RR], bot[RR];
#pragma unroll
    for (int i = 0; i < RR; i++) { top[i] = -CUDART_INF_F; bot[i] = CUDART_INF_F; }

    for (int inst = gw; inst < NN; inst += WARPS_PER_BATCH) {
        const float4* __restrict__ xp =
            reinterpret_cast<const float4*>(xb + (long long)inst * LL);

        float4 v0 = xp[0 * 32 + lane];
        float4 v1 = xp[1 * 32 + lane];
        float4 v2 = xp[2 * 32 + lane];
        float4 v3 = xp[3 * 32 + lane];

        float acc = 0.0f;
        acc = fmaf(v0.x, w0.x,  acc); acc = fmaf(v0.y, w0.y,  acc);
        acc = fmaf(v0.z, w0.z,  acc); acc = fmaf(v0.w, w0.w,  acc);
        acc = fmaf(v1.x, w1r.x, acc); acc = fmaf(v1.y, w1r.y, acc);
        acc = fmaf(v1.z, w1r.z, acc); acc = fmaf(v1.w, w1r.w, acc);
        acc = fmaf(v2.x, w2r.x, acc); acc = fmaf(v2.y, w2r.y, acc);
        acc = fmaf(v2.z, w2r.z, acc); acc = fmaf(v2.w, w2r.w, acc);
        acc = fmaf(v3.x, w3r.x, acc); acc = fmaf(v3.y, w3r.y, acc);
        acc = fmaf(v3.z, w3r.z, acc); acc = fmaf(v3.w, w3r.w, acc);

#pragma unroll
        for (int o = 16; o; o >>= 1)
            acc += __shfl_xor_sync(0xffffffff, acc, o);

        if (lane == 0) {
            float v = acc + cb;
            insert_max(top, v);
            insert_min(bot, v);
        }
    }

    if (lane == 0) {
#pragma unroll
        for (int j = 0; j < RR; j++) {
            stop[warp * RR + j] = top[j];
            sbot[warp * RR + j] = bot[j];
        }
    }
    __syncthreads();

    if (tid == 0) {
        float ft[RR], fb[RR];
#pragma unroll
        for (int i = 0; i < RR; i++) { ft[i] = -CUDART_INF_F; fb[i] = CUDART_INF_F; }
        for (int i = 0; i < WPB * RR; i++) {
            insert_max(ft, stop[i]);
            insert_min(fb, sbot[i]);
        }
        float* pt = g_part_top + ((long long)b * GPB + blockIdx.x) * RR;
        float* pb = g_part_bot + ((long long)b * GPB + blockIdx.x) * RR;
#pragma unroll
        for (int j = 0; j < RR; j++) { pt[j] = ft[j]; pb[j] = fb[j]; }
    }
}

// ---------------------------------------------------------------------------
// Merge kernel v3: stage + log-depth tournament + 20-FMA matvec. grid = BB.
// ---------------------------------------------------------------------------
__global__ __launch_bounds__(256) void chowder_merge_mlp_kernel(
    float* __restrict__ out)
{
    const int b   = blockIdx.x;
    const int tid = threadIdx.x;

    __shared__ float stop[GPB * RR];
    __shared__ float sbot[GPB * RR];
    __shared__ float cat[2 * RR];
    __shared__ float sWe[2 * RR * CC];
    __shared__ float sbe[CC];

    // prefetch collapsed weights concurrently with partial staging
    if (tid >= 224 && tid < 224 + 2 * RR * CC) sWe[tid - 224] = g_Weff[tid - 224];
    if (tid >= 248 && tid < 248 + CC)          sbe[tid - 248] = g_beff[tid - 248];

    // stage partials into shared: coalesced, one latency exposure
    {
        const float* pt = g_part_top + (long long)b * GPB * RR;
        const float* pb = g_part_bot + (long long)b * GPB * RR;
#pragma unroll
        for (int i = tid; i < GPB * RR; i += 256) {
            stop[i] = pt[i];
            sbot[i] = pb[i];
        }
    }
    __syncthreads();

    // tournament: 256 sorted 5-lists -> 1, 8 levels
    for (int cnt = GPB; cnt > 1; cnt >>= 1) {
        int half = cnt >> 1;
        if (tid < half) {
            float a[RR], c[RR], o[RR];
#pragma unroll
            for (int j = 0; j < RR; j++) { a[j] = stop[tid * RR + j]; c[j] = stop[(tid + half) * RR + j]; }
            merge_desc5(a, c, o);
#pragma unroll
            for (int j = 0; j < RR; j++) stop[tid * RR + j] = o[j];

#pragma unroll
            for (int j = 0; j < RR; j++) { a[j] = sbot[tid * RR + j]; c[j] = sbot[(tid + half) * RR + j]; }
            merge_asc5(a, c, o);
#pragma unroll
            for (int j = 0; j < RR; j++) sbot[tid * RR + j] = o[j];
        }
        __syncthreads();
    }

    // cat = [min_vals ascending, max_vals descending]
    if (tid < RR)          cat[tid] = sbot[tid];
    else if (tid < 2 * RR) cat[tid] = stop[tid - RR];
    __syncthreads();

    // out = cat @ W_eff + b_eff  (20 FMAs)
    if (tid < CC) {
        float a = sbe[tid];
#pragma unroll
        for (int i = 0; i < 2 * RR; i++)
            a = fmaf(cat[i], sWe[i * CC + tid], a);
        out[b * CC + tid] = a;
    }
}

// ---------------------------------------------------------------------------
extern "C" void kernel_launch(void* const* d_in, const int* in_sizes, int n_in,
                              void* d_out, int out_size)
{
    const float* x      = (const float*)d_in[0];
    const float* conv_w = (const float*)d_in[1];
    const float* conv_b = (const float*)d_in[2];
    const float* w1     = (const float*)d_in[3];
    const float* b1     = (const float*)d_in[4];
    const float* w2     = (const float*)d_in[5];
    const float* b2     = (const float*)d_in[6];
    const float* w3     = (const float*)d_in[7];
    const float* b3     = (const float*)d_in[8];
    float* out          = (float*)d_out;

    dim3 grid(GPB, BB + 1);   // extra block row: MLP collapse, overlapped
    chowder_scores_topk_kernel<<<grid, 256>>>(x, conv_w, conv_b,
                                              w1, b1, w2, b2, w3, b3);
    chowder_merge_mlp_kernel<<<BB, 256>>>(out);
}